// round 4
// baseline (speedup 1.0000x reference)
#include <cuda_runtime.h>
#include <stdint.h>
#include <math.h>

#define N_   2048
#define B_   2
#define C_   512
#define BN   (B_*N_)
#define EPSF 1e-8f
#define BIGF 1e9f

// ---------------- device scratch (no allocation allowed) ----------------
__device__ float g_nrm1[BN], g_nrm2[BN];
__device__ float g_f1n[BN*C_], g_f2n[BN*C_];
__device__ float g_xy11[BN*2];
__device__ int   g_nbA[BN*12], g_nbB[BN*12];
__device__ int   g_cand[BN*4];
__device__ float g_Kc[BN*4];
__device__ int   g_sord[BN];                 // per-row slot permutation sorted by cand j
__device__ int   g_ccnt[B_*N_], g_coff[B_*N_], g_ccur[B_*N_];
__device__ int   g_tlist[B_*N_*4];           // transpose entries: (i<<2)|c, sorted by i per column
__device__ int   g_idx0[BN], g_idxA[BN], g_maskA[BN], g_idx1[BN], g_mask[BN];
__device__ float g_flow[BN*2], g_fgri[BN*2];
__device__ float g_rowD2[BN*2];
__device__ int   g_rowIdx[BN*2];
__device__ int   g_colArg[BN];
__device__ float g_par[2];   // [0]=eps, [1]=power

// ---------------- small helpers ----------------
__global__ void k_params(const float* gam, const float* eps){
  float e = __fadd_rn(expf(eps[0]), 0.03f);
  float g = expf(gam[0]);
  g_par[0] = e;
  g_par[1] = __fdiv_rn(g, __fadd_rn(g, e));
}

__global__ void k_norms(const float* __restrict__ f1, const float* __restrict__ f2){
  int w = (blockIdx.x*blockDim.x + threadIdx.x) >> 5;
  int lane = threadIdx.x & 31;
  if (w >= 2*BN) return;
  const float* f = (w < BN) ? (f1 + (size_t)w*C_) : (f2 + (size_t)(w-BN)*C_);
  float s = 0.f;
  for (int c = lane; c < C_; c += 32) s = __fmaf_rn(f[c], f[c], s);
  #pragma unroll
  for (int off=16; off; off>>=1) s = __fadd_rn(s, __shfl_xor_sync(0xffffffffu, s, off));
  if (lane == 0){
    float n = __fadd_rn(sqrtf(s), EPSF);
    if (w < BN) g_nrm1[w] = n; else g_nrm2[w-BN] = n;
  }
}

__global__ void k_normalize(const float* __restrict__ f1, const float* __restrict__ f2){
  int e = blockIdx.x*blockDim.x + threadIdx.x;
  const int tot = BN*C_;
  if (e < tot){
    g_f1n[e] = __fdiv_rn(f1[e], g_nrm1[e / C_]);
  } else if (e < 2*tot){
    int e2 = e - tot;
    g_f2n[e2] = __fdiv_rn(f2[e2], g_nrm2[e2 / C_]);
  }
}

__global__ void k_xy11(const float* __restrict__ xy1, int useflow){
  int e = blockIdx.x*blockDim.x + threadIdx.x;
  if (e >= BN*2) return;
  g_xy11[e] = useflow ? __fadd_rn(xy1[e], g_fgri[e]) : xy1[e];
}

// XLA-style FMA-contracted squared distance: aa = fma(y,y,x*x), dot = fma(y,y',x*x'),
// d = max((aa+bb) - 2*dot, 0)
__device__ __forceinline__ float sqd_fma(float qx, float qy, float qa, float rx, float ry){
  float rb = __fmaf_rn(ry, ry, __fmul_rn(rx, rx));
  float dt = __fmaf_rn(qy, ry, __fmul_rn(qx, rx));
  return fmaxf(__fsub_rn(__fadd_rn(qa, rb), __fmul_rn(2.0f, dt)), 0.0f);
}

// ---------------- warp-per-row brute force top-K (smallest keys) ----------------
// key = (f32bits(d_mod) << 32) | j  : smaller distance first, jax lowest-index tie-break.
template<int K, bool MASKC, bool EYE, bool SQRT>
__device__ __forceinline__ void warp_topk(
    const float* __restrict__ q, const float* __restrict__ ref,
    const int* __restrict__ maskc, int row, unsigned long long (&out)[K])
{
  int lane = threadIdx.x & 31;
  int b = row / N_, i = row - b*N_;
  float qx = q[row*2], qy = q[row*2+1];
  float qa = __fmaf_rn(qy, qy, __fmul_rn(qx, qx));
  const float2* R = (const float2*)ref + (size_t)b*N_;
  const int* M = MASKC ? (maskc + b*N_) : nullptr;

  unsigned long long best[K];
  #pragma unroll
  for (int s=0; s<K; s++) best[s] = 0xFFFFFFFFFFFFFFFFull;

  for (int t=0; t<N_/32; t++){
    int j = lane + 32*t;
    float2 rr = __ldg(&R[j]);
    float d = sqd_fma(qx, qy, qa, rr.x, rr.y);
    if (MASKC){ if (!__ldg(&M[j])) d = BIGF; }
    if (EYE){ if (j == i) d = __fadd_rn(d, BIGF); }
    if (SQRT){ d = sqrtf(__fadd_rn(d, EPSF)); }   // rank on D like the reference
    unsigned long long key = ((unsigned long long)__float_as_uint(d) << 32) | (unsigned)j;
    if (key < best[K-1]){
      best[K-1] = key;
      #pragma unroll
      for (int s=K-1; s>0; s--){
        if (best[s] < best[s-1]){
          unsigned long long tmp = best[s-1]; best[s-1] = best[s]; best[s] = tmp;
        } else break;
      }
    }
  }
  // warp k-way merge of 32 sorted lists; keys globally unique.
  #pragma unroll
  for (int s=0; s<K; s++){
    unsigned long long c = best[0];
    unsigned long long m = c;
    #pragma unroll
    for (int off=16; off; off>>=1){
      unsigned long long o = __shfl_xor_sync(0xffffffffu, m, off);
      m = (o < m) ? o : m;
    }
    if (c == m){
      #pragma unroll
      for (int u=0; u<K-1; u++) best[u] = best[u+1];
      best[K-1] = 0xFFFFFFFFFFFFFFFFull;
    }
    out[s] = m;
  }
}

template<int K, bool SQRT>
__global__ void k_knn_write(const float* __restrict__ q, const float* __restrict__ ref,
                            int* __restrict__ oIdx, float* __restrict__ oD){
  int row = blockIdx.x*(blockDim.x>>5) + (threadIdx.x>>5);
  if (row >= BN) return;
  unsigned long long out[K];
  warp_topk<K,false,false,SQRT>(q, ref, nullptr, row, out);
  if ((threadIdx.x & 31) == 0){
    #pragma unroll
    for (int s=0; s<K; s++){
      oIdx[row*K+s] = (int)(out[s] & 0xFFFFFFFFu);
      if (oD) oD[row*K+s] = __uint_as_float((unsigned)(out[s] >> 32));
    }
  }
}

// ---------------- feature-cost: one thread per (row, cand), sequential fma (cublas-like) ----
__global__ void k_kc(){
  int e = blockIdx.x*blockDim.x + threadIdx.x;
  if (e >= BN*4) return;
  int w = e >> 2, c = e & 3;
  int b = w / N_;
  int j = g_cand[w*4+c];
  const float* f1 = g_f1n + (size_t)w*C_;
  const float* f2 = g_f2n + ((size_t)(b*N_ + j))*C_;
  float s = 0.f;
  #pragma unroll 8
  for (int k=0; k<C_; k++) s = __fmaf_rn(f1[k], __ldg(&f2[k]), s);
  float Cmv = __fsub_rn(1.0f, s);
  g_Kc[w*4+c] = expf(__fdiv_rn(-Cmv, g_par[0]));
  if (c == 0){
    // slot permutation sorted by candidate column index ascending
    int k0 = (g_cand[w*4+0]<<2)|0, k1 = (g_cand[w*4+1]<<2)|1;
    int k2 = (g_cand[w*4+2]<<2)|2, k3 = (g_cand[w*4+3]<<2)|3;
    int t;
    if (k0>k1){t=k0;k0=k1;k1=t;} if (k2>k3){t=k2;k2=k3;k3=t;}
    if (k0>k2){t=k0;k0=k2;k2=t;} if (k1>k3){t=k1;k1=k3;k3=t;}
    if (k1>k2){t=k1;k1=k2;k2=t;}
    g_sord[w] = (k0&3) | ((k1&3)<<2) | ((k2&3)<<4) | ((k3&3)<<6);
  }
}

// ---------------- transpose-list build (deterministic column sums) ----------------
__global__ void k_ct_zero(){
  int e = blockIdx.x*blockDim.x + threadIdx.x;
  if (e < B_*N_) g_ccnt[e] = 0;
}
__global__ void k_ct_count(){
  int row = blockIdx.x*blockDim.x + threadIdx.x;
  if (row >= BN) return;
  int b = row / N_;
  #pragma unroll
  for (int c=0; c<4; c++) atomicAdd(&g_ccnt[b*N_ + g_cand[row*4+c]], 1);
}
__global__ void k_ct_scan(){   // one 32-thread block per batch
  int b = blockIdx.x, lane = threadIdx.x;
  int base = b*N_, lo = lane*64;
  int tot = 0;
  for (int t=0; t<64; t++) tot += g_ccnt[base+lo+t];
  int inc = tot;
  #pragma unroll
  for (int off=1; off<32; off<<=1){
    int v = __shfl_up_sync(0xffffffffu, inc, off);
    if (lane >= off) inc += v;
  }
  int run = inc - tot;   // exclusive
  for (int t=0; t<64; t++){
    g_coff[base+lo+t] = run;
    g_ccur[base+lo+t] = run;
    run += g_ccnt[base+lo+t];
  }
}
__global__ void k_ct_scatter(){
  int row = blockIdx.x*blockDim.x + threadIdx.x;
  if (row >= BN) return;
  int b = row / N_, i = row - b*N_;
  #pragma unroll
  for (int c=0; c<4; c++){
    int j = g_cand[row*4+c];
    int pos = atomicAdd(&g_ccur[b*N_+j], 1);
    g_tlist[b*N_*4 + pos] = (i<<2) | c;
  }
}
__global__ void k_ct_sort(){   // per-column insertion sort by row index
  int col = blockIdx.x*blockDim.x + threadIdx.x;
  if (col >= B_*N_) return;
  int b = col / N_;
  int off = g_coff[col], cnt = g_ccnt[col];
  int* L = g_tlist + b*N_*4 + off;
  for (int a2=1; a2<cnt; a2++){
    int v = L[a2]; int p = a2-1;
    while (p >= 0 && L[p] > v){ L[p+1] = L[p]; p--; }
    L[p+1] = v;
  }
}

// ---------------- fused sparse sinkhorn (5 iters) + mutual-best recon ----------------
__global__ void k_sinkhorn(int dr0){
  __shared__ float su[N_], sv[N_];
  __shared__ unsigned long long ck[N_];
  int b = blockIdx.x, tid = threadIdx.x;
  const int* cb = g_cand + b*N_*4;
  const float* Kb = g_Kc + b*N_*4;
  const int* sob = g_sord + b*N_;
  const int* tl = g_tlist + b*N_*4;
  const float P = 1.0f/2048.0f;
  float pw = g_par[1];

  sv[tid] = 1.f; sv[tid+1024] = 1.f;
  __syncthreads();

  for (int t=0; t<5; t++){
    // u update: sum over candidates in ascending-j order (matches dense K@v)
    #pragma unroll
    for (int rr=0; rr<2; rr++){
      int i = tid + rr*1024;
      int o = sob[i];
      float s = 0.f;
      #pragma unroll
      for (int p=0; p<4; p++){
        int sl = (o >> (2*p)) & 3;
        if (sl < dr0)
          s = __fmaf_rn(Kb[i*4+sl], sv[cb[i*4+sl]], s);
      }
      su[i] = powf(__fdiv_rn(P, __fadd_rn(s, EPSF)), pw);
    }
    __syncthreads();
    // v update: column sums in ascending-i order via sorted transpose list
    #pragma unroll
    for (int rr=0; rr<2; rr++){
      int j = tid + rr*1024;
      int off = g_coff[b*N_+j], cnt = g_ccnt[b*N_+j];
      float s = 0.f;
      for (int p=0; p<cnt; p++){
        int e = tl[off+p];
        int c = e & 3;
        if (c < dr0){
          int i = e >> 2;
          s = __fmaf_rn(Kb[i*4+c], su[i], s);
        }
      }
      sv[j] = powf(__fdiv_rn(P, __fadd_rn(s, EPSF)), pw);
    }
    __syncthreads();
  }

  // column argmax of T = u*K*v (tie -> smallest row i); init = (val 0, i=0) like jax.
  ck[tid] = 0xFFFFFFFFull; ck[tid+1024] = 0xFFFFFFFFull;
  __syncthreads();
  #pragma unroll
  for (int rr=0; rr<2; rr++){
    int i = tid + rr*1024;
    float ui = su[i];
    for (int c=0; c<dr0; c++){
      int j = cb[i*4+c];
      float tv = __fmul_rn(__fmul_rn(ui, Kb[i*4+c]), sv[j]);
      unsigned long long key = ((unsigned long long)__float_as_uint(tv) << 32)
                             | (unsigned)(~(unsigned)i);
      atomicMax(&ck[j], key);
    }
  }
  __syncthreads();
  // row top-2 (value, tie -> smallest col j) + mutual + ratio test
  #pragma unroll
  for (int rr=0; rr<2; rr++){
    int i = tid + rr*1024;
    float ui = su[i];
    unsigned long long k0 = 0ull, k1 = 0ull;
    for (int c=0; c<dr0; c++){
      int j = cb[i*4+c];
      float tv = __fmul_rn(__fmul_rn(ui, Kb[i*4+c]), sv[j]);
      unsigned long long key = ((unsigned long long)__float_as_uint(tv) << 32)
                             | (unsigned)(~(unsigned)j);
      if (key > k0){ k1 = k0; k0 = key; }
      else if (key > k1){ k1 = key; }
    }
    float rv0 = __uint_as_float((unsigned)(k0 >> 32));
    float rv1 = __uint_as_float((unsigned)(k1 >> 32)); // 0 when dr0==1 (zeros fill)
    int bj = (int)(~(unsigned)k0);
    int bi = (int)(~(unsigned)ck[bj]);
    bool ok = rv0 > __fmul_rn(1.2f, rv1);
    g_idx0[b*N_ + i] = (bi == i && ok) ? bj : -1;
  }
}

// ---------------- knn_match recon (row top2 + col argmin precomputed, D-space) ------
__global__ void k_knnrecon(){
  int row = blockIdx.x*blockDim.x + threadIdx.x;
  if (row >= BN) return;
  int b = row / N_, i = row - b*N_;
  float d0 = g_rowD2[row*2];      // already sqrt(d2+EPS)
  float d1 = g_rowD2[row*2+1];
  int bj = g_rowIdx[row*2];
  bool ok = __fmul_rn(d0, 1.2f) < d1;
  bool mut = (g_colArg[b*N_ + bj] == i);
  g_idx0[row] = (ok && mut) ? bj : -1;
}

// ---------------- merge + similarity verify (+ pre-outlier flow/mask) ----------------
template<int SIMK>
__global__ void k_simmerge(const float* __restrict__ xy1, const float* __restrict__ xy2,
                           int first){
  int row = blockIdx.x*blockDim.x + threadIdx.x;
  if (row >= BN) return;
  int b = row / N_, i = row - b*N_;
  int m;
  if (first) m = g_idx0[row];
  else { int p = g_idx1[row]; m = (p == 0) ? g_idx0[row] : (p - 1); }

  int outv = -1;
  if (m >= 0){
    const float* X1 = xy1 + (size_t)b*N_*2;
    const float* X2 = xy2 + (size_t)b*N_*2;
    float pix = X1[i*2], piy = X1[i*2+1];
    float pjx = X2[m*2], pjy = X2[m*2+1];
    float o1x[SIMK], o1y[SIMK], o2x[SIMK], o2y[SIMK];
    #pragma unroll
    for (int k=0; k<SIMK; k++){
      int a = g_nbA[row*12 + 1 + k];
      o1x[k] = __fsub_rn(X1[a*2],   pix);
      o1y[k] = __fsub_rn(X1[a*2+1], piy);
      int c = g_nbB[(b*N_+m)*12 + 1 + k];
      o2x[k] = __fsub_rn(X2[c*2],   pjx);
      o2y[k] = __fsub_rn(X2[c*2+1], pjy);
    }
    float colmin[SIMK];
    #pragma unroll
    for (int l=0; l<SIMK; l++) colmin[l] = 3.4e38f;
    float sum1 = 0.f;
    #pragma unroll
    for (int k=0; k<SIMK; k++){
      float rmn = 3.4e38f;
      #pragma unroll
      for (int l=0; l<SIMK; l++){
        float dx = __fsub_rn(o1x[k], o2x[l]);
        float dy = __fsub_rn(o1y[k], o2y[l]);
        float d = sqrtf(__fadd_rn(__fmaf_rn(dy, dy, __fmul_rn(dx, dx)), EPSF));
        rmn = fminf(rmn, d);
        colmin[l] = fminf(colmin[l], d);
      }
      sum1 = __fadd_rn(sum1, rmn);
    }
    float sum2 = 0.f;
    #pragma unroll
    for (int l=0; l<SIMK; l++) sum2 = __fadd_rn(sum2, colmin[l]);
    float Kf = (float)SIMK;
    float cham = __fmul_rn(0.5f, __fadd_rn(__fdiv_rn(sum1, Kf), __fdiv_rn(sum2, Kf)));
    if (cham <= 2.0f) outv = m;
  }
  g_idxA[row] = outv;
  int mm = (outv >= 0);
  g_maskA[row] = mm;
  int j = (outv >= 0) ? outv : 0;
  float mf = (float)mm;
  g_flow[row*2]   = __fmul_rn(__fsub_rn(xy2[(b*N_+j)*2],   xy1[row*2]),   mf);
  g_flow[row*2+1] = __fmul_rn(__fsub_rn(xy2[(b*N_+j)*2+1], xy1[row*2+1]), mf);
}

// ---------------- masked KNN(8) + outlier rejection, fused ----------------
__global__ void k_outlier(const float* __restrict__ xy1){
  int row = blockIdx.x*(blockDim.x>>5) + (threadIdx.x>>5);
  if (row >= BN) return;
  unsigned long long out[8];
  warp_topk<8,true,true,false>(xy1, xy1, g_maskA, row, out);
  if ((threadIdx.x & 31) == 0){
    int b = row / N_;
    float fx = g_flow[row*2], fy = g_flow[row*2+1];
    float sx = 0.f, sy = 0.f, cnt = 0.f;
    #pragma unroll
    for (int s=0; s<8; s++){
      float d = __uint_as_float((unsigned)(out[s] >> 32));
      int j = (int)(out[s] & 0xFFFFFFFFu);
      float vf = (d < 5e8f) ? 1.0f : 0.0f;
      sx = __fmaf_rn(g_flow[(b*N_+j)*2],   vf, sx);
      sy = __fmaf_rn(g_flow[(b*N_+j)*2+1], vf, sy);
      cnt = __fadd_rn(cnt, vf);
    }
    float dv = fmaxf(cnt, 1.0f);
    float mx = __fdiv_rn(sx, dv), my = __fdiv_rn(sy, dv);
    float ddx = __fsub_rn(fx, mx), ddy = __fsub_rn(fy, my);
    float dev = sqrtf(__fadd_rn(__fmaf_rn(ddy, ddy, __fmul_rn(ddx, ddx)), EPSF));
    int m = g_maskA[row];
    bool keep = m && ((cnt > 0.0f) ? (dev <= 2.0f) : true);
    g_idx1[row] = keep ? (g_idxA[row] + 1) : 0;
  }
}

// ---------------- dedup (one block per batch) ----------------
__global__ void k_dedup(){
  __shared__ int cnt[N_+1];
  int b = blockIdx.x, tid = threadIdx.x;
  for (int s = tid; s < N_+1; s += 1024) cnt[s] = 0;
  __syncthreads();
  int v0 = g_idx1[b*N_ + tid], v1 = g_idx1[b*N_ + tid + 1024];
  atomicAdd(&cnt[v0], 1); atomicAdd(&cnt[v1], 1);
  __syncthreads();
  if (cnt[v0] > 1) g_idx1[b*N_ + tid] = 0;
  if (cnt[v1] > 1) g_idx1[b*N_ + tid + 1024] = 0;
}

// ---------------- finish: final flow + mask (optionally to d_out) ----------------
__global__ void k_finish(const float* __restrict__ xy1, const float* __restrict__ xy2,
                         float* __restrict__ outp, int withmask){
  int row = blockIdx.x*blockDim.x + threadIdx.x;
  if (row >= BN) return;
  int b = row / N_;
  int v = g_idx1[row];
  int mm = (v != 0);
  int j = (v - 1) * mm;
  float mf = (float)mm;
  float fx = __fmul_rn(__fsub_rn(xy2[(b*N_+j)*2],   xy1[row*2]),   mf);
  float fy = __fmul_rn(__fsub_rn(xy2[(b*N_+j)*2+1], xy1[row*2+1]), mf);
  g_flow[row*2] = fx; g_flow[row*2+1] = fy;
  g_mask[row] = mm;
  if (outp){
    outp[row*2] = fx; outp[row*2+1] = fy;
    if (withmask) outp[2*BN + row] = mf;
  }
}

// ---------------- griddata: masked KNN(4) + IDW interpolation, fused ----------------
__global__ void k_griddata(const float* __restrict__ xy1){
  int row = blockIdx.x*(blockDim.x>>5) + (threadIdx.x>>5);
  if (row >= BN) return;
  unsigned long long out[4];
  warp_topk<4,true,false,false>(xy1, xy1, g_mask, row, out);
  if ((threadIdx.x & 31) == 0){
    int b = row / N_;
    float ws = 0.f, sx = 0.f, sy = 0.f;
    #pragma unroll
    for (int s=0; s<4; s++){
      float d = __uint_as_float((unsigned)(out[s] >> 32));
      int j = (int)(out[s] & 0xFFFFFFFFu);
      float vf = (d < 5e8f) ? 1.0f : 0.0f;
      float w = __fdiv_rn(vf, __fadd_rn(d, 1e-6f));
      sx = __fmaf_rn(w, g_flow[(b*N_+j)*2],   sx);
      sy = __fmaf_rn(w, g_flow[(b*N_+j)*2+1], sy);
      ws = __fadd_rn(ws, w);
    }
    float ix = __fdiv_rn(sx, __fadd_rn(ws, EPSF));
    float iy = __fdiv_rn(sy, __fadd_rn(ws, EPSF));
    int m = g_mask[row];
    g_fgri[row*2]   = m ? g_flow[row*2]   : ix;
    g_fgri[row*2+1] = m ? g_flow[row*2+1] : iy;
  }
}

// ---------------- host orchestration ----------------
extern "C" void kernel_launch(void* const* d_in, const int* in_sizes, int n_in,
                              void* d_out, int out_size){
  const float* xy1 = (const float*)d_in[0];
  const float* xy2 = (const float*)d_in[1];
  const float* f1  = (const float*)d_in[2];
  const float* f2  = (const float*)d_in[3];
  const float* gam = (const float*)d_in[4];
  const float* eps = (const float*)d_in[5];
  float* outp = (float*)d_out;
  int withmask = (out_size >= BN*3) ? 1 : 0;

  float *p_xy11, *p_rowD2;
  int *p_nbA, *p_nbB, *p_cand, *p_rowIdx, *p_colArg;
  cudaGetSymbolAddress((void**)&p_xy11,   g_xy11);
  cudaGetSymbolAddress((void**)&p_nbA,    g_nbA);
  cudaGetSymbolAddress((void**)&p_nbB,    g_nbB);
  cudaGetSymbolAddress((void**)&p_cand,   g_cand);
  cudaGetSymbolAddress((void**)&p_rowD2,  g_rowD2);
  cudaGetSymbolAddress((void**)&p_rowIdx, g_rowIdx);
  cudaGetSymbolAddress((void**)&p_colArg, g_colArg);

  const int WB = 256;            // 8 warps/block for warp-per-row kernels
  const int GW = BN/8;           // 512 blocks
  const int TB = 256, GT = (BN+TB-1)/TB;

  k_params<<<1,1>>>(gam, eps);
  k_norms<<<(2*BN*32)/256, 256>>>(f1, f2);
  k_normalize<<<(2*BN*C_ + 255)/256, 256>>>(f1, f2);
  k_knn_write<12,false><<<GW, WB>>>(xy1, xy1, p_nbA, nullptr);   // self KNN xy1 (k=12)
  k_knn_write<12,false><<<GW, WB>>>(xy2, xy2, p_nbB, nullptr);   // self KNN xy2 (k=12)

  // ---- two sinkhorn matching passes ----
  for (int pass = 0; pass < 2; pass++){
    k_xy11<<<(BN*2+255)/256, 256>>>(xy1, pass);                  // pass0: flow=0
    k_knn_write<4,false><<<GW, WB>>>(p_xy11, xy2, p_cand, nullptr);
    k_kc<<<(BN*4+255)/256, 256>>>();
    k_ct_zero<<<(B_*N_+255)/256, 256>>>();
    k_ct_count<<<GT, TB>>>();
    k_ct_scan<<<B_, 32>>>();
    k_ct_scatter<<<GT, TB>>>();
    k_ct_sort<<<(B_*N_+255)/256, 256>>>();
    for (int r = 0; r < 4; r++){
      k_sinkhorn<<<2, 1024>>>(r + 1);
      k_simmerge<8><<<GT, TB>>>(xy1, xy2, r == 0);
      k_outlier<<<GW, WB>>>(xy1);
      if (r > 0) k_dedup<<<2, 1024>>>();
    }
    k_finish<<<GT, TB>>>(xy1, xy2, nullptr, 0);
    k_griddata<<<GW, WB>>>(xy1);
  }

  // ---- two KNN matching passes ----
  for (int pass = 0; pass < 2; pass++){
    int final = (pass == 1);
    k_xy11<<<(BN*2+255)/256, 256>>>(xy1, 1);
    k_knn_write<2,true><<<GW, WB>>>(p_xy11, xy2, p_rowIdx, p_rowD2);  // row top-2 (D space)
    k_knn_write<1,true><<<GW, WB>>>(xy2, p_xy11, p_colArg, nullptr);  // col argmin (D space)
    k_knnrecon<<<GT, TB>>>();
    k_simmerge<11><<<GT, TB>>>(xy1, xy2, 1);
    k_outlier<<<GW, WB>>>(xy1);
    k_finish<<<GT, TB>>>(xy1, xy2, final ? outp : nullptr, withmask);
    if (!final) k_griddata<<<GW, WB>>>(xy1);
  }
}

// round 5
// speedup vs baseline: 1.0367x; 1.0367x over previous
#include <cuda_runtime.h>
#include <stdint.h>
#include <math.h>

#define N_   2048
#define B_   2
#define C_   512
#define BN   (B_*N_)
#define EPSF 1e-8f
#define BIGF 1e9f

// ---------------- device scratch (no allocation allowed) ----------------
__device__ float  g_nrm1[BN], g_nrm2[BN];
__device__ float  g_f1n[BN*C_], g_f2n[BN*C_];
__device__ float4 g_xy1p[BN], g_xy2p[BN], g_xy11p[BN];   // (x, y, rb, 0)
__device__ int    g_nbA[BN*12], g_nbB[BN*12];
__device__ int    g_cand[BN*4];
__device__ float  g_Kc[BN*4];
__device__ int    g_sord[BN];
__device__ int    g_ccnt[B_*N_], g_coff[B_*N_];
__device__ int    g_tlist[B_*N_*4];
__device__ int    g_idx0[BN], g_idxA[BN], g_maskA[BN], g_idx1[BN], g_mask[BN];
__device__ float  g_flow[BN*2], g_fgri[BN*2];
__device__ float  g_rowD[BN*2];
__device__ int    g_rowIdx[BN*2];
__device__ int    g_colArg[BN];
__device__ float  g_par[2];   // [0]=eps, [1]=power

__global__ void k_params(const float* gam, const float* eps){
  float e = __fadd_rn(expf(eps[0]), 0.03f);
  float g = expf(gam[0]);
  g_par[0] = e;
  g_par[1] = __fdiv_rn(g, __fadd_rn(g, e));
}

__global__ void k_norms(const float* __restrict__ f1, const float* __restrict__ f2){
  int w = (blockIdx.x*blockDim.x + threadIdx.x) >> 5;
  int lane = threadIdx.x & 31;
  if (w >= 2*BN) return;
  const float* f = (w < BN) ? (f1 + (size_t)w*C_) : (f2 + (size_t)(w-BN)*C_);
  float s = 0.f;
  for (int c = lane; c < C_; c += 32) s = __fmaf_rn(f[c], f[c], s);
  #pragma unroll
  for (int off=16; off; off>>=1) s = __fadd_rn(s, __shfl_xor_sync(0xffffffffu, s, off));
  if (lane == 0){
    float n = __fadd_rn(sqrtf(s), EPSF);
    if (w < BN) g_nrm1[w] = n; else g_nrm2[w-BN] = n;
  }
}

__global__ void k_normalize(const float* __restrict__ f1, const float* __restrict__ f2){
  int e = blockIdx.x*blockDim.x + threadIdx.x;
  const int tot = BN*C_;
  if (e < tot){
    g_f1n[e] = __fdiv_rn(f1[e], g_nrm1[e / C_]);
  } else if (e < 2*tot){
    int e2 = e - tot;
    g_f2n[e2] = __fdiv_rn(f2[e2], g_nrm2[e2 / C_]);
  }
}

// prep: build (x, y, rb, 0); rb = fma(y,y, x*x) identical to reference contraction
__global__ void k_prep(const float* __restrict__ xy, float4* __restrict__ dst, int addflow){
  int p = blockIdx.x*blockDim.x + threadIdx.x;
  if (p >= BN) return;
  float x = xy[p*2], y = xy[p*2+1];
  if (addflow){ x = __fadd_rn(x, g_fgri[p*2]); y = __fadd_rn(y, g_fgri[p*2+1]); }
  dst[p] = make_float4(x, y, __fmaf_rn(y, y, __fmul_rn(x, x)), 0.f);
}

// ---------------- warp-per-row brute force top-K with fp32 screening ----------------
// key = (f32bits(d) << 32) | j : min-K == reference top_k(-d) with lowest-index ties.
template<int K, bool MASKC, bool EYE, bool SQRT>
__device__ __forceinline__ void warp_topk(
    const float4* __restrict__ Q, const float4* __restrict__ R,
    const int* __restrict__ maskc, int row, unsigned long long (&out)[K])
{
  int lane = threadIdx.x & 31;
  int b = row / N_, i = row - b*N_;
  float4 q = __ldg(&Q[row]);            // q.z = qa
  const float4* Rb = R + (size_t)b*N_;
  const int* M = MASKC ? (maskc + b*N_) : nullptr;

  unsigned long long best[K];
  #pragma unroll
  for (int s=0; s<K; s++) best[s] = 0x7F800000FFFFFFFFull;  // d=+inf
  float dlast = __uint_as_float(0x7F800000u);               // +inf (non-SQRT screen)
  float U     = __uint_as_float(0x7FC00000u);                // NaN -> SQRT screen never skips

  #pragma unroll 4
  for (int t=0; t<N_/32; t++){
    int j = lane + 32*t;
    float4 r = __ldg(&Rb[j]);
    float dt = __fmaf_rn(q.y, r.y, __fmul_rn(q.x, r.x));
    float d  = fmaxf(__fsub_rn(__fadd_rn(q.z, r.z), __fmul_rn(2.0f, dt)), 0.0f);
    if (MASKC){ if (!__ldg(&M[j])) d = BIGF; }
    if (EYE){ if (j == i) d = __fadd_rn(d, BIGF); }
    bool try_ins;
    if (SQRT){
      // skip only when provably sqrt_rn(d+EPS) > Dlast
      float d2pe = __fadd_rn(d, EPSF);
      try_ins = !(d2pe > U);
      if (try_ins) d = sqrtf(d2pe);
    } else {
      try_ins = (d <= dlast);
    }
    if (try_ins){
      unsigned long long key = ((unsigned long long)__float_as_uint(d) << 32) | (unsigned)j;
      if (key < best[K-1]){
        best[K-1] = key;
        #pragma unroll
        for (int s=K-1; s>0; s--){
          if (best[s] < best[s-1]){
            unsigned long long tmp = best[s-1]; best[s-1] = best[s]; best[s] = tmp;
          } else break;
        }
        unsigned hb = (unsigned)(best[K-1] >> 32);
        if (SQRT){
          float up = __uint_as_float(hb + 1);   // nextafter(Dlast,+inf); inf->NaN (safe)
          U = __fmul_ru(up, up);
        } else {
          dlast = __uint_as_float(hb);
        }
      }
    }
  }
  // warp k-way merge of 32 sorted lists; keys globally unique.
  #pragma unroll
  for (int s=0; s<K; s++){
    unsigned long long c = best[0];
    unsigned long long m = c;
    #pragma unroll
    for (int off=16; off; off>>=1){
      unsigned long long o = __shfl_xor_sync(0xffffffffu, m, off);
      m = (o < m) ? o : m;
    }
    if (c == m){
      #pragma unroll
      for (int u=0; u<K-1; u++) best[u] = best[u+1];
      best[K-1] = 0x7F800000FFFFFFFFull;
    }
    out[s] = m;
  }
}

template<int K, bool SQRT>
__global__ void k_knn_write(const float4* __restrict__ Q, const float4* __restrict__ R,
                            int* __restrict__ oIdx, float* __restrict__ oD){
  int row = blockIdx.x*(blockDim.x>>5) + (threadIdx.x>>5);
  if (row >= BN) return;
  unsigned long long out[K];
  warp_topk<K,false,false,SQRT>(Q, R, nullptr, row, out);
  if ((threadIdx.x & 31) == 0){
    #pragma unroll
    for (int s=0; s<K; s++){
      oIdx[row*K+s] = (int)(out[s] & 0xFFFFFFFFu);
      if (oD) oD[row*K+s] = __uint_as_float((unsigned)(out[s] >> 32));
    }
  }
}

// ---------------- feature-cost: one thread per (row, cand), sequential fma ----------
__global__ void k_kc(){
  int e = blockIdx.x*blockDim.x + threadIdx.x;
  if (e >= BN*4) return;
  int w = e >> 2, c = e & 3;
  int b = w / N_;
  int j = g_cand[w*4+c];
  const float* f1 = g_f1n + (size_t)w*C_;
  const float* f2 = g_f2n + ((size_t)(b*N_ + j))*C_;
  float s = 0.f;
  #pragma unroll 8
  for (int k=0; k<C_; k++) s = __fmaf_rn(f1[k], __ldg(&f2[k]), s);
  float Cmv = __fsub_rn(1.0f, s);
  g_Kc[w*4+c] = expf(__fdiv_rn(-Cmv, g_par[0]));
  if (c == 0){
    int k0 = (g_cand[w*4+0]<<2)|0, k1 = (g_cand[w*4+1]<<2)|1;
    int k2 = (g_cand[w*4+2]<<2)|2, k3 = (g_cand[w*4+3]<<2)|3;
    int t;
    if (k0>k1){t=k0;k0=k1;k1=t;} if (k2>k3){t=k2;k2=k3;k3=t;}
    if (k0>k2){t=k0;k0=k2;k2=t;} if (k1>k3){t=k1;k1=k3;k3=t;}
    if (k1>k2){t=k1;k1=k2;k2=t;}
    g_sord[w] = (k0&3) | ((k1&3)<<2) | ((k2&3)<<4) | ((k3&3)<<6);
  }
}

// ---------------- fused transpose-list build (one block per batch) ----------------
__global__ void k_ctbuild(){
  __shared__ int scnt[N_];
  __shared__ int scur[N_];
  int b = blockIdx.x, tid = threadIdx.x;   // 1024 threads
  scnt[tid] = 0; scnt[tid+1024] = 0;
  __syncthreads();
  #pragma unroll
  for (int rr=0; rr<2; rr++){
    int i = tid + rr*1024;
    #pragma unroll
    for (int c=0; c<4; c++) atomicAdd(&scnt[g_cand[(b*N_+i)*4+c]], 1);
  }
  __syncthreads();
  if (tid < 32){
    int lo = tid*64, tot = 0;
    for (int t=0; t<64; t++) tot += scnt[lo+t];
    int inc = tot;
    #pragma unroll
    for (int off=1; off<32; off<<=1){
      int v = __shfl_up_sync(0xffffffffu, inc, off);
      if (tid >= off) inc += v;
    }
    int run = inc - tot;
    for (int t=0; t<64; t++){
      g_coff[b*N_+lo+t] = run;
      scur[lo+t] = run;
      g_ccnt[b*N_+lo+t] = scnt[lo+t];
      run += scnt[lo+t];
    }
  }
  __syncthreads();
  #pragma unroll
  for (int rr=0; rr<2; rr++){
    int i = tid + rr*1024;
    #pragma unroll
    for (int c=0; c<4; c++){
      int j = g_cand[(b*N_+i)*4+c];
      int pos = atomicAdd(&scur[j], 1);
      g_tlist[b*N_*4 + pos] = (i<<2) | c;
    }
  }
  __syncthreads();
  #pragma unroll
  for (int rr=0; rr<2; rr++){
    int col = tid + rr*1024;
    int off = g_coff[b*N_+col], cnt = g_ccnt[b*N_+col];
    int* L = g_tlist + b*N_*4 + off;
    for (int a2=1; a2<cnt; a2++){
      int v = L[a2]; int p = a2-1;
      while (p >= 0 && L[p] > v){ L[p+1] = L[p]; p--; }
      L[p+1] = v;
    }
  }
}

// ---------------- fused sparse sinkhorn (5 iters) + mutual-best recon ----------------
__global__ void k_sinkhorn(int dr0){
  __shared__ float su[N_], sv[N_];
  __shared__ unsigned long long ck[N_];
  int b = blockIdx.x, tid = threadIdx.x;
  const int* cb = g_cand + b*N_*4;
  const float* Kb = g_Kc + b*N_*4;
  const int* sob = g_sord + b*N_;
  const int* tl = g_tlist + b*N_*4;
  const float P = 1.0f/2048.0f;
  float pw = g_par[1];

  sv[tid] = 1.f; sv[tid+1024] = 1.f;
  __syncthreads();

  for (int t=0; t<5; t++){
    #pragma unroll
    for (int rr=0; rr<2; rr++){
      int i = tid + rr*1024;
      int o = sob[i];
      float s = 0.f;
      #pragma unroll
      for (int p=0; p<4; p++){
        int sl = (o >> (2*p)) & 3;
        if (sl < dr0)
          s = __fmaf_rn(Kb[i*4+sl], sv[cb[i*4+sl]], s);
      }
      su[i] = powf(__fdiv_rn(P, __fadd_rn(s, EPSF)), pw);
    }
    __syncthreads();
    #pragma unroll
    for (int rr=0; rr<2; rr++){
      int j = tid + rr*1024;
      int off = g_coff[b*N_+j], cnt = g_ccnt[b*N_+j];
      float s = 0.f;
      for (int p=0; p<cnt; p++){
        int e = tl[off+p];
        int c = e & 3;
        if (c < dr0){
          int i = e >> 2;
          s = __fmaf_rn(Kb[i*4+c], su[i], s);
        }
      }
      sv[j] = powf(__fdiv_rn(P, __fadd_rn(s, EPSF)), pw);
    }
    __syncthreads();
  }

  ck[tid] = 0xFFFFFFFFull; ck[tid+1024] = 0xFFFFFFFFull;
  __syncthreads();
  #pragma unroll
  for (int rr=0; rr<2; rr++){
    int i = tid + rr*1024;
    float ui = su[i];
    for (int c=0; c<dr0; c++){
      int j = cb[i*4+c];
      float tv = __fmul_rn(__fmul_rn(ui, Kb[i*4+c]), sv[j]);
      unsigned long long key = ((unsigned long long)__float_as_uint(tv) << 32)
                             | (unsigned)(~(unsigned)i);
      atomicMax(&ck[j], key);
    }
  }
  __syncthreads();
  #pragma unroll
  for (int rr=0; rr<2; rr++){
    int i = tid + rr*1024;
    float ui = su[i];
    unsigned long long k0 = 0ull, k1 = 0ull;
    for (int c=0; c<dr0; c++){
      int j = cb[i*4+c];
      float tv = __fmul_rn(__fmul_rn(ui, Kb[i*4+c]), sv[j]);
      unsigned long long key = ((unsigned long long)__float_as_uint(tv) << 32)
                             | (unsigned)(~(unsigned)j);
      if (key > k0){ k1 = k0; k0 = key; }
      else if (key > k1){ k1 = key; }
    }
    float rv0 = __uint_as_float((unsigned)(k0 >> 32));
    float rv1 = __uint_as_float((unsigned)(k1 >> 32));
    int bj = (int)(~(unsigned)k0);
    int bi = (int)(~(unsigned)ck[bj]);
    bool ok = rv0 > __fmul_rn(1.2f, rv1);
    g_idx0[b*N_ + i] = (bi == i && ok) ? bj : -1;
  }
}

// ---------------- merge (+optional knn recon) + similarity verify ----------------
// MODE: 0 = idx0 only (first round), 1 = merge idx0 into idx1, 2 = knn recon
template<int SIMK, int MODE>
__global__ void k_simmerge(const float* __restrict__ xy1, const float* __restrict__ xy2){
  int row = blockIdx.x*blockDim.x + threadIdx.x;
  if (row >= BN) return;
  int b = row / N_, i = row - b*N_;
  int m;
  if (MODE == 0) m = g_idx0[row];
  else if (MODE == 1){ int p = g_idx1[row]; m = (p == 0) ? g_idx0[row] : (p - 1); }
  else {
    float d0 = g_rowD[row*2], d1 = g_rowD[row*2+1];
    int bj = g_rowIdx[row*2];
    bool ok = __fmul_rn(d0, 1.2f) < d1;
    bool mut = (g_colArg[b*N_ + bj] == i);
    m = (ok && mut) ? bj : -1;
  }

  int outv = -1;
  if (m >= 0){
    const float* X1 = xy1 + (size_t)b*N_*2;
    const float* X2 = xy2 + (size_t)b*N_*2;
    float pix = X1[i*2], piy = X1[i*2+1];
    float pjx = X2[m*2], pjy = X2[m*2+1];
    float o1x[SIMK], o1y[SIMK], o2x[SIMK], o2y[SIMK];
    #pragma unroll
    for (int k=0; k<SIMK; k++){
      int a = g_nbA[row*12 + 1 + k];
      o1x[k] = __fsub_rn(X1[a*2],   pix);
      o1y[k] = __fsub_rn(X1[a*2+1], piy);
      int c = g_nbB[(b*N_+m)*12 + 1 + k];
      o2x[k] = __fsub_rn(X2[c*2],   pjx);
      o2y[k] = __fsub_rn(X2[c*2+1], pjy);
    }
    float colmin[SIMK];
    #pragma unroll
    for (int l=0; l<SIMK; l++) colmin[l] = 3.4e38f;
    float sum1 = 0.f;
    #pragma unroll
    for (int k=0; k<SIMK; k++){
      float rmn = 3.4e38f;
      #pragma unroll
      for (int l=0; l<SIMK; l++){
        float dx = __fsub_rn(o1x[k], o2x[l]);
        float dy = __fsub_rn(o1y[k], o2y[l]);
        float d = sqrtf(__fadd_rn(__fmaf_rn(dy, dy, __fmul_rn(dx, dx)), EPSF));
        rmn = fminf(rmn, d);
        colmin[l] = fminf(colmin[l], d);
      }
      sum1 = __fadd_rn(sum1, rmn);
    }
    float sum2 = 0.f;
    #pragma unroll
    for (int l=0; l<SIMK; l++) sum2 = __fadd_rn(sum2, colmin[l]);
    float Kf = (float)SIMK;
    float cham = __fmul_rn(0.5f, __fadd_rn(__fdiv_rn(sum1, Kf), __fdiv_rn(sum2, Kf)));
    if (cham <= 2.0f) outv = m;
  }
  g_idxA[row] = outv;
  int mm = (outv >= 0);
  g_maskA[row] = mm;
  int j = (outv >= 0) ? outv : 0;
  float mf = (float)mm;
  g_flow[row*2]   = __fmul_rn(__fsub_rn(xy2[(b*N_+j)*2],   xy1[row*2]),   mf);
  g_flow[row*2+1] = __fmul_rn(__fsub_rn(xy2[(b*N_+j)*2+1], xy1[row*2+1]), mf);
}

// ---------------- masked KNN(8) + outlier rejection, fused ----------------
__global__ void k_outlier(){
  int row = blockIdx.x*(blockDim.x>>5) + (threadIdx.x>>5);
  if (row >= BN) return;
  unsigned long long out[8];
  warp_topk<8,true,true,false>(g_xy1p, g_xy1p, g_maskA, row, out);
  if ((threadIdx.x & 31) == 0){
    int b = row / N_;
    float fx = g_flow[row*2], fy = g_flow[row*2+1];
    float sx = 0.f, sy = 0.f, cnt = 0.f;
    #pragma unroll
    for (int s=0; s<8; s++){
      float d = __uint_as_float((unsigned)(out[s] >> 32));
      int j = (int)(out[s] & 0xFFFFFFFFu);
      float vf = (d < 5e8f) ? 1.0f : 0.0f;
      sx = __fmaf_rn(g_flow[(b*N_+j)*2],   vf, sx);
      sy = __fmaf_rn(g_flow[(b*N_+j)*2+1], vf, sy);
      cnt = __fadd_rn(cnt, vf);
    }
    float dv = fmaxf(cnt, 1.0f);
    float mx = __fdiv_rn(sx, dv), my = __fdiv_rn(sy, dv);
    float ddx = __fsub_rn(fx, mx), ddy = __fsub_rn(fy, my);
    float dev = sqrtf(__fadd_rn(__fmaf_rn(ddy, ddy, __fmul_rn(ddx, ddx)), EPSF));
    int m = g_maskA[row];
    bool keep = m && ((cnt > 0.0f) ? (dev <= 2.0f) : true);
    g_idx1[row] = keep ? (g_idxA[row] + 1) : 0;
  }
}

__global__ void k_dedup(){
  __shared__ int cnt[N_+1];
  int b = blockIdx.x, tid = threadIdx.x;
  for (int s = tid; s < N_+1; s += 1024) cnt[s] = 0;
  __syncthreads();
  int v0 = g_idx1[b*N_ + tid], v1 = g_idx1[b*N_ + tid + 1024];
  atomicAdd(&cnt[v0], 1); atomicAdd(&cnt[v1], 1);
  __syncthreads();
  if (cnt[v0] > 1) g_idx1[b*N_ + tid] = 0;
  if (cnt[v1] > 1) g_idx1[b*N_ + tid + 1024] = 0;
}

__global__ void k_finish(const float* __restrict__ xy1, const float* __restrict__ xy2,
                         float* __restrict__ outp, int withmask){
  int row = blockIdx.x*blockDim.x + threadIdx.x;
  if (row >= BN) return;
  int b = row / N_;
  int v = g_idx1[row];
  int mm = (v != 0);
  int j = (v - 1) * mm;
  float mf = (float)mm;
  float fx = __fmul_rn(__fsub_rn(xy2[(b*N_+j)*2],   xy1[row*2]),   mf);
  float fy = __fmul_rn(__fsub_rn(xy2[(b*N_+j)*2+1], xy1[row*2+1]), mf);
  g_flow[row*2] = fx; g_flow[row*2+1] = fy;
  g_mask[row] = mm;
  if (outp){
    outp[row*2] = fx; outp[row*2+1] = fy;
    if (withmask) outp[2*BN + row] = mf;
  }
}

__global__ void k_griddata(){
  int row = blockIdx.x*(blockDim.x>>5) + (threadIdx.x>>5);
  if (row >= BN) return;
  unsigned long long out[4];
  warp_topk<4,true,false,false>(g_xy1p, g_xy1p, g_mask, row, out);
  if ((threadIdx.x & 31) == 0){
    int b = row / N_;
    float ws = 0.f, sx = 0.f, sy = 0.f;
    #pragma unroll
    for (int s=0; s<4; s++){
      float d = __uint_as_float((unsigned)(out[s] >> 32));
      int j = (int)(out[s] & 0xFFFFFFFFu);
      float vf = (d < 5e8f) ? 1.0f : 0.0f;
      float w = __fdiv_rn(vf, __fadd_rn(d, 1e-6f));
      sx = __fmaf_rn(w, g_flow[(b*N_+j)*2],   sx);
      sy = __fmaf_rn(w, g_flow[(b*N_+j)*2+1], sy);
      ws = __fadd_rn(ws, w);
    }
    float ix = __fdiv_rn(sx, __fadd_rn(ws, EPSF));
    float iy = __fdiv_rn(sy, __fadd_rn(ws, EPSF));
    int m = g_mask[row];
    g_fgri[row*2]   = m ? g_flow[row*2]   : ix;
    g_fgri[row*2+1] = m ? g_flow[row*2+1] : iy;
  }
}

// ---------------- host orchestration ----------------
extern "C" void kernel_launch(void* const* d_in, const int* in_sizes, int n_in,
                              void* d_out, int out_size){
  const float* xy1 = (const float*)d_in[0];
  const float* xy2 = (const float*)d_in[1];
  const float* f1  = (const float*)d_in[2];
  const float* f2  = (const float*)d_in[3];
  const float* gam = (const float*)d_in[4];
  const float* eps = (const float*)d_in[5];
  float* outp = (float*)d_out;
  int withmask = (out_size >= BN*3) ? 1 : 0;

  float4 *p_xy1p, *p_xy2p, *p_xy11p;
  float *p_rowD;
  int *p_nbA, *p_nbB, *p_cand, *p_rowIdx, *p_colArg;
  cudaGetSymbolAddress((void**)&p_xy1p,   g_xy1p);
  cudaGetSymbolAddress((void**)&p_xy2p,   g_xy2p);
  cudaGetSymbolAddress((void**)&p_xy11p,  g_xy11p);
  cudaGetSymbolAddress((void**)&p_nbA,    g_nbA);
  cudaGetSymbolAddress((void**)&p_nbB,    g_nbB);
  cudaGetSymbolAddress((void**)&p_cand,   g_cand);
  cudaGetSymbolAddress((void**)&p_rowD,   g_rowD);
  cudaGetSymbolAddress((void**)&p_rowIdx, g_rowIdx);
  cudaGetSymbolAddress((void**)&p_colArg, g_colArg);

  const int WB = 256;            // 8 warps/block for warp-per-row kernels
  const int GW = BN/8;           // 512 blocks
  const int TB = 256, GT = (BN+TB-1)/TB;

  k_params<<<1,1>>>(gam, eps);
  k_norms<<<(2*BN*32)/256, 256>>>(f1, f2);
  k_normalize<<<(2*BN*C_ + 255)/256, 256>>>(f1, f2);
  k_prep<<<GT, TB>>>(xy1, p_xy1p, 0);
  k_prep<<<GT, TB>>>(xy2, p_xy2p, 0);
  k_knn_write<12,false><<<GW, WB>>>(p_xy1p, p_xy1p, p_nbA, nullptr);
  k_knn_write<12,false><<<GW, WB>>>(p_xy2p, p_xy2p, p_nbB, nullptr);

  // ---- two sinkhorn matching passes ----
  for (int pass = 0; pass < 2; pass++){
    const float4* qp = p_xy1p;
    if (pass){ k_prep<<<GT, TB>>>(xy1, p_xy11p, 1); qp = p_xy11p; }
    k_knn_write<4,false><<<GW, WB>>>(qp, p_xy2p, p_cand, nullptr);
    k_kc<<<(BN*4+127)/128, 128>>>();
    k_ctbuild<<<B_, 1024>>>();
    for (int r = 0; r < 4; r++){
      k_sinkhorn<<<2, 1024>>>(r + 1);
      if (r == 0) k_simmerge<8,0><<<GT, TB>>>(xy1, xy2);
      else        k_simmerge<8,1><<<GT, TB>>>(xy1, xy2);
      k_outlier<<<GW, WB>>>();
      if (r > 0) k_dedup<<<2, 1024>>>();
    }
    k_finish<<<GT, TB>>>(xy1, xy2, nullptr, 0);
    k_griddata<<<GW, WB>>>();
  }

  // ---- two KNN matching passes ----
  for (int pass = 0; pass < 2; pass++){
    int final = (pass == 1);
    k_prep<<<GT, TB>>>(xy1, p_xy11p, 1);
    k_knn_write<2,true><<<GW, WB>>>(p_xy11p, p_xy2p, p_rowIdx, p_rowD);   // row top-2 (D)
    k_knn_write<1,true><<<GW, WB>>>(p_xy2p, p_xy11p, p_colArg, nullptr);  // col argmin (D)
    k_simmerge<11,2><<<GT, TB>>>(xy1, xy2);
    k_outlier<<<GW, WB>>>();
    k_finish<<<GT, TB>>>(xy1, xy2, final ? outp : nullptr, withmask);
    if (!final) k_griddata<<<GW, WB>>>();
  }
}